// round 4
// baseline (speedup 1.0000x reference)
#include <cuda_runtime.h>
#include <cuda_bf16.h>

#define FULL 0xffffffffu

// ---- packed f32x2 helpers (Blackwell; FFMA2 only reachable via PTX) ----
__device__ __forceinline__ unsigned long long pk2(float lo, float hi) {
    unsigned long long r;
    asm("mov.b64 %0, {%1, %2};" : "=l"(r) : "f"(lo), "f"(hi));
    return r;
}
__device__ __forceinline__ unsigned long long fma2(unsigned long long a,
                                                   unsigned long long b,
                                                   unsigned long long c) {
    unsigned long long r;
    asm("fma.rn.f32x2 %0, %1, %2, %3;" : "=l"(r) : "l"(a), "l"(b), "l"(c));
    return r;
}
__device__ __forceinline__ void upk2(unsigned long long v, float& lo, float& hi) {
    asm("mov.b64 {%0, %1}, %2;" : "=f"(lo), "=f"(hi) : "l"(v));
}

// Per-warp histogram update: match lanes with equal idx, elected leader does a
// plain (non-atomic) shared RMW — leaders of distinct values hit distinct
// addresses, and invalid lanes carry a sentinel that never stores.
__device__ __forceinline__ void hupd(unsigned* hw, int base, int idx,
                                     bool valid, int lane) {
    unsigned m = __match_any_sync(FULL, idx);
    int leader = __ffs(m) - 1;
    if (valid && lane == leader) {
        hw[base + idx] += (unsigned)__popc(m);
    }
}

struct Tok {
    float p0, p1, p2, c0, c1;
    int i0, i1, i2, i3, i4, j0, j1;
};

__device__ __forceinline__ Tok loadtok(const float* __restrict__ cont_p,
                                       const float* __restrict__ cont_c,
                                       const int* __restrict__ cat_p,
                                       const int* __restrict__ cat_c,
                                       int rowbase, int t, bool valid) {
    Tok k;
    k.p0 = k.p1 = k.p2 = k.c0 = k.c1 = 0.f;
    k.i0 = k.i1 = k.i2 = k.i3 = k.i4 = k.j0 = k.j1 = 999;
    if (valid) {
        const float* cp = cont_p + (rowbase + t) * 3;
        k.p0 = cp[0]; k.p1 = cp[1]; k.p2 = cp[2];
        float2 cc = *reinterpret_cast<const float2*>(cont_c + (rowbase + t) * 2);
        k.c0 = cc.x; k.c1 = cc.y;
        const int* ip = cat_p + (rowbase + t) * 5;
        k.i0 = ip[0]; k.i1 = ip[1]; k.i2 = ip[2]; k.i3 = ip[3]; k.i4 = ip[4];
        int2 jc = *reinterpret_cast<const int2*>(cat_c + (rowbase + t) * 2);
        k.j0 = jc.x; k.j1 = jc.y;
    }
    return k;
}

__global__ void __launch_bounds__(128)
mlp_row_kernel(const float* __restrict__ cont_p, const float* __restrict__ cont_c,
               const int* __restrict__ cat_p, const int* __restrict__ cat_c,
               const int* __restrict__ lengths,
               const float* __restrict__ w_p1, const float* __restrict__ b_p1,
               const float* __restrict__ w_p2, const float* __restrict__ b_p2,
               const float* __restrict__ w_c1, const float* __restrict__ b_c1,
               const float* __restrict__ w_c2, const float* __restrict__ b_c2,
               const float* __restrict__ emb_gender, const float* __restrict__ emb_korean,
               const float* __restrict__ emb_primary, const float* __restrict__ emb_job,
               const float* __restrict__ emb_rep, const float* __restrict__ emb_place,
               const float* __restrict__ emb_add,
               const float* __restrict__ w_fc1, const float* __restrict__ b_fc1,
               const float* __restrict__ w_fc2, const float* __restrict__ b_fc2,
               float* __restrict__ out, int S, int B)
{
    // All state is WARP-PRIVATE: one warp processes one row end-to-end.
    // Histogram layout (101 counters):
    // gender@0(2) korean@2(2) primary@4(2) job@6(11) rep@17(34) place@51(19) add@70(31)
    __shared__ unsigned hist_s[4][104];
    __shared__ float4 stageX[4][2][32];   // (p0, c0, p1, c1), double-buffered
    __shared__ float2 stageY[4][2][32];   // (p2, 0)
    __shared__ float  xbuf[4][128];       // pooled vector [ep | ec | hp | hc]

    const int tid  = threadIdx.x;
    const int lane = tid & 31;
    const int w    = tid >> 5;
    const int row  = blockIdx.x * 4 + w;
    if (row >= B) return;

    const int len = lengths[row];
    const int rowbase = row * S;
    unsigned* hw = hist_s[w];
    for (int i = lane; i < 104; i += 32) hw[i] = 0u;

    // lane = output channel d; first-layer weights packed (p-side, c-side)
    const unsigned long long wA = pk2(w_p1[lane],      w_c1[lane]);
    const unsigned long long wB = pk2(w_p1[32 + lane], w_c1[32 + lane]);
    const unsigned long long wC = pk2(w_p1[64 + lane], 0.f);
    const unsigned long long bias2 = pk2(b_p1[lane], b_c1[lane]);

    __syncwarp();

    float accp = 0.f, accc = 0.f;
    int t0 = 0, buf = 0;

    // Prefetch chunk 0 (len >= 1 always).
    Tok cur = loadtok(cont_p, cont_c, cat_p, cat_c, rowbase, lane, lane < len);

    while (true) {
        const int nv = min(32, len - t0);
        if (lane < nv) {
            stageX[w][buf][lane] = make_float4(cur.p0, cur.c0, cur.p1, cur.c1);
            stageY[w][buf][lane] = make_float2(cur.p2, 0.f);
        }

        // Category histograms (warp-aggregated, no atomics)
        const bool valid = lane < nv;
        hupd(hw, 0,  cur.i0, valid, lane);
        hupd(hw, 2,  cur.i1, valid, lane);
        hupd(hw, 4,  cur.i2, valid, lane);
        hupd(hw, 6,  cur.i3, valid, lane);
        hupd(hw, 17, cur.i4, valid, lane);
        hupd(hw, 51, cur.j0, valid, lane);
        hupd(hw, 70, cur.j1, valid, lane);

        // Prefetch next chunk's globals BEFORE consuming the stage, so the
        // ~550-cycle DRAM latency overlaps the j-loop below.
        const int t1 = t0 + 32;
        const bool have_next = t1 < len;
        Tok nxt = loadtok(cont_p, cont_c, cat_p, cat_c, rowbase, t1 + lane,
                          have_next && (lane < len - t1));

        __syncwarp();   // STS -> LDS ordering for this buffer

        // LDS.128/LDS.64 broadcast token j; each lane computes its (p, c)
        // channel pair via packed FFMA2, accumulating post-relu sums.
        #pragma unroll 8
        for (int j = 0; j < nv; j++) {
            float4 x = stageX[w][buf][j];
            float2 y = stageY[w][buf][j];
            unsigned long long a01 = pk2(x.x, x.y);
            unsigned long long a23 = pk2(x.z, x.w);
            unsigned long long ayy = pk2(y.x, y.y);
            unsigned long long tpc = fma2(a01, wA, bias2);
            tpc = fma2(a23, wB, tpc);
            tpc = fma2(ayy, wC, tpc);
            float tp, tc;
            upk2(tpc, tp, tc);
            accp += fmaxf(tp, 0.f);
            accc += fmaxf(tc, 0.f);
        }

        if (!have_next) break;
        cur = nxt;
        t0 = t1;
        buf ^= 1;
    }

    // ---- per-warp epilogue (lane = channel d) ----
    const float invlen = 1.0f / (float)len;
    const int d = lane;

    // Second linears: broadcast pooled pre-activations via SHFL.
    const float up = accp * invlen;
    const float uc = accc * invlen;
    float hp = b_p2[d], hc = b_c2[d];
    #pragma unroll
    for (int e = 0; e < 32; e++) {
        hp = fmaf(__shfl_sync(FULL, up, e), w_p2[e * 32 + d], hp);
        hc = fmaf(__shfl_sync(FULL, uc, e), w_c2[e * 32 + d], hc);
    }

    // Embedding means from histogram counts (2 accumulators to cut chain depth).
    float sa = 0.f, sb = 0.f;
    #pragma unroll
    for (int v = 0; v < 2; v++)  sa = fmaf((float)hw[v],      emb_gender[v * 32 + d], sa);
    #pragma unroll
    for (int v = 0; v < 2; v++)  sb = fmaf((float)hw[2 + v],  emb_korean[v * 32 + d], sb);
    #pragma unroll
    for (int v = 0; v < 2; v++)  sa = fmaf((float)hw[4 + v],  emb_primary[v * 32 + d], sa);
    #pragma unroll
    for (int v = 0; v < 11; v++) {
        if (v & 1) sb = fmaf((float)hw[6 + v], emb_job[v * 32 + d], sb);
        else       sa = fmaf((float)hw[6 + v], emb_job[v * 32 + d], sa);
    }
    #pragma unroll
    for (int v = 0; v < 34; v++) {
        if (v & 1) sb = fmaf((float)hw[17 + v], emb_rep[v * 32 + d], sb);
        else       sa = fmaf((float)hw[17 + v], emb_rep[v * 32 + d], sa);
    }
    const float ep = (sa + sb) * invlen * 0.2f;

    float ta = 0.f, tb = 0.f;
    #pragma unroll
    for (int v = 0; v < 19; v++) {
        if (v & 1) tb = fmaf((float)hw[51 + v], emb_place[v * 32 + d], tb);
        else       ta = fmaf((float)hw[51 + v], emb_place[v * 32 + d], ta);
    }
    #pragma unroll
    for (int v = 0; v < 31; v++) {
        if (v & 1) tb = fmaf((float)hw[70 + v], emb_add[v * 32 + d], tb);
        else       ta = fmaf((float)hw[70 + v], emb_add[v * 32 + d], ta);
    }
    const float ec = (ta + tb) * invlen * 0.5f;

    // Stage pooled vector x = [ep | ec | hp | hc] in warp-private shared.
    float* xb = xbuf[w];
    xb[d] = ep; xb[32 + d] = ec; xb[64 + d] = hp; xb[96 + d] = hc;
    __syncwarp();

    // fc1: 128 -> 64 (2 outputs per lane), split accumulators for ILP.
    float a0a = b_fc1[d],      a0b = 0.f;
    float a1a = b_fc1[32 + d], a1b = 0.f;
    #pragma unroll 8
    for (int i = 0; i < 128; i += 2) {
        float x0 = xb[i], x1 = xb[i + 1];
        a0a = fmaf(x0, w_fc1[i * 64 + d], a0a);
        a1a = fmaf(x0, w_fc1[i * 64 + 32 + d], a1a);
        a0b = fmaf(x1, w_fc1[(i + 1) * 64 + d], a0b);
        a1b = fmaf(x1, w_fc1[(i + 1) * 64 + 32 + d], a1b);
    }
    const float h0 = fmaxf(a0a + a0b, 0.f);
    const float h1 = fmaxf(a1a + a1b, 0.f);

    // fc2: 64 -> 2, warp tree-reduce.
    float s0 = h0 * w_fc2[d * 2]     + h1 * w_fc2[(32 + d) * 2];
    float s1 = h0 * w_fc2[d * 2 + 1] + h1 * w_fc2[(32 + d) * 2 + 1];
    #pragma unroll
    for (int off = 16; off; off >>= 1) {
        s0 += __shfl_xor_sync(FULL, s0, off);
        s1 += __shfl_xor_sync(FULL, s1, off);
    }
    if (lane == 0) {
        out[row * 2]     = fmaxf(s0 + b_fc2[0], 0.f);
        out[row * 2 + 1] = fmaxf(s1 + b_fc2[1], 0.f);
    }
}

extern "C" void kernel_launch(void* const* d_in, const int* in_sizes, int n_in,
                              void* d_out, int out_size)
{
    const float* cont_p   = (const float*)d_in[0];
    const float* cont_c   = (const float*)d_in[1];
    const int*   cat_p    = (const int*)  d_in[2];
    const int*   cat_c    = (const int*)  d_in[3];
    const int*   lengths  = (const int*)  d_in[4];
    const float* w_p1     = (const float*)d_in[5];
    const float* b_p1     = (const float*)d_in[6];
    const float* w_p2     = (const float*)d_in[7];
    const float* b_p2     = (const float*)d_in[8];
    const float* w_c1     = (const float*)d_in[9];
    const float* b_c1     = (const float*)d_in[10];
    const float* w_c2     = (const float*)d_in[11];
    const float* b_c2     = (const float*)d_in[12];
    const float* emb_gender  = (const float*)d_in[13];
    const float* emb_korean  = (const float*)d_in[14];
    const float* emb_primary = (const float*)d_in[15];
    const float* emb_job     = (const float*)d_in[16];
    const float* emb_rep     = (const float*)d_in[17];
    const float* emb_place   = (const float*)d_in[18];
    const float* emb_add     = (const float*)d_in[19];
    const float* w_fc1    = (const float*)d_in[20];
    const float* b_fc1    = (const float*)d_in[21];
    const float* w_fc2    = (const float*)d_in[22];
    const float* b_fc2    = (const float*)d_in[23];
    float* out = (float*)d_out;

    const int B = in_sizes[4];                 // lengths: [B]
    const int S = in_sizes[0] / (B * 3);       // cont_p: [B,S,3]

    const int grid = (B + 3) / 4;              // one warp per row, 4 rows/block
    mlp_row_kernel<<<grid, 128>>>(cont_p, cont_c, cat_p, cat_c, lengths,
                                  w_p1, b_p1, w_p2, b_p2, w_c1, b_c1, w_c2, b_c2,
                                  emb_gender, emb_korean, emb_primary, emb_job,
                                  emb_rep, emb_place, emb_add,
                                  w_fc1, b_fc1, w_fc2, b_fc2, out, S, B);
}

// round 5
// speedup vs baseline: 1.0010x; 1.0010x over previous
#include <cuda_runtime.h>
#include <cuda_bf16.h>

#define FULL 0xffffffffu

// Per-warp histogram update: match lanes with equal idx, elected leader does a
// plain (non-atomic) shared RMW. Invalid lanes carry sentinel 999 (they match
// only each other; their leader's store is suppressed).
__device__ __forceinline__ void hupd(unsigned* hw, int base, int idx, int lane) {
    unsigned m = __match_any_sync(FULL, idx);
    int leader = __ffs(m) - 1;
    if (lane == leader && idx != 999) {
        hw[base + idx] += (unsigned)__popc(m);
    }
}

__global__ void __launch_bounds__(128)
mlp_row_kernel(const float* __restrict__ cont_p, const float* __restrict__ cont_c,
               const int* __restrict__ cat_p, const int* __restrict__ cat_c,
               const int* __restrict__ lengths,
               const float* __restrict__ w_p1, const float* __restrict__ b_p1,
               const float* __restrict__ w_p2, const float* __restrict__ b_p2,
               const float* __restrict__ w_c1, const float* __restrict__ b_c1,
               const float* __restrict__ w_c2, const float* __restrict__ b_c2,
               const float* __restrict__ emb_gender, const float* __restrict__ emb_korean,
               const float* __restrict__ emb_primary, const float* __restrict__ emb_job,
               const float* __restrict__ emb_rep, const float* __restrict__ emb_place,
               const float* __restrict__ emb_add,
               const float* __restrict__ w_fc1, const float* __restrict__ b_fc1,
               const float* __restrict__ w_fc2, const float* __restrict__ b_fc2,
               float* __restrict__ out, int S, int B)
{
    // One warp owns one row end-to-end. All warp state is private.
    // Histogram layout (101 counters):
    // gender@0(2) korean@2(2) primary@4(2) job@6(11) rep@17(34) place@51(19) add@70(31)
    __shared__ float4   rawp_s[4][2][24];  // cont_p chunk raw: 32 tok x 3 f = 384B
    __shared__ int4     rawk_s[4][2][40];  // cat_p  chunk raw: 32 tok x 5 i = 640B
    __shared__ float4   stX[4][2][32];     // stage: (p0, c0, p1, c1)
    __shared__ float2   stY[4][2][32];     // stage: (p2, 0)
    __shared__ unsigned hist_s[4][104];
    __shared__ float4   xb4[4][32];        // pooled vector [ep | ec | hp | hc]

    const int tid  = threadIdx.x;
    const int lane = tid & 31;
    const int w    = tid >> 5;
    const int row  = blockIdx.x * 4 + w;
    if (row >= B) return;

    const int len = lengths[row];
    const int rowbase = row * S;
    unsigned* hw = hist_s[w];
    for (int i = lane; i < 104; i += 32) hw[i] = 0u;

    // lane = output channel d; first-layer weights in registers (scalar).
    const float wp0 = w_p1[lane];
    const float wp1 = w_p1[32 + lane];
    const float wp2 = w_p1[64 + lane];
    const float bp  = b_p1[lane];
    const float wc0 = w_c1[lane];
    const float wc1 = w_c1[32 + lane];
    const float bc  = b_c1[lane];

    __syncwarp();

    // Hoisted, lane-adjusted chunk pointers (advance by constant strides).
    // Chunks always cover a full 32 tokens; t0 <= S-32 so over-read stays
    // inside this row's allocation.
    const float4* gp  = reinterpret_cast<const float4*>(cont_p + (size_t)rowbase * 3) + lane;
    const int4*   gk0 = reinterpret_cast<const int4*>(cat_p + (size_t)rowbase * 5) + lane;
    const int4*   gk1 = gk0 + 32;
    const float2* gc  = reinterpret_cast<const float2*>(cont_c) + rowbase + lane;
    const int2*   gj  = reinterpret_cast<const int2*>(cat_c) + rowbase + lane;

    // Prefetch chunk 0 (len >= 1 always).
    float4 rp = make_float4(0.f, 0.f, 0.f, 0.f);
    int4   rk0, rk1 = make_int4(0, 0, 0, 0);
    float2 rc;
    int2   rj;
    if (lane < 24) rp = gp[0];
    rk0 = gk0[0];
    if (lane < 8) rk1 = gk1[0];
    rc = gc[0];
    rj = gj[0];

    float accp = 0.f, accc = 0.f;
    int t0 = 0, buf = 0;

    while (true) {
        const int nv = min(32, len - t0);
        const bool valid = lane < nv;

        // Park raw chunk into shared (coalesced STS.128).
        if (lane < 24) rawp_s[w][buf][lane] = rp;
        rawk_s[w][buf][lane] = rk0;
        if (lane < 8) rawk_s[w][buf][32 + lane] = rk1;
        const float2 ccur = rc;
        int2 jcur = rj;

        // Prefetch next chunk before consuming this one (hide DRAM latency).
        const bool have_next = (t0 + 32) < len;
        if (have_next) {
            gp += 24; gk0 += 40; gk1 += 40; gc += 32; gj += 32;
            if (lane < 24) rp = gp[0];
            rk0 = gk0[0];
            if (lane < 8) rk1 = gk1[0];
            rc = gc[0];
            rj = gj[0];
        }
        __syncwarp();   // raw STS -> redistribute LDS

        // Redistribute: lane t reads its token's AoS from shared
        // (stride-3 and stride-5 are conflict-free mod 32).
        const float* rpf = reinterpret_cast<const float*>(rawp_s[w][buf]);
        const float p0 = rpf[lane * 3];
        const float p1 = rpf[lane * 3 + 1];
        const float p2 = rpf[lane * 3 + 2];
        const int* rki = reinterpret_cast<const int*>(rawk_s[w][buf]);
        int i0 = rki[lane * 5];
        int i1 = rki[lane * 5 + 1];
        int i2 = rki[lane * 5 + 2];
        int i3 = rki[lane * 5 + 3];
        int i4 = rki[lane * 5 + 4];
        if (!valid) { i0 = i1 = i2 = i3 = i4 = 999; jcur.x = 999; jcur.y = 999; }

        // Category histograms (warp-aggregated, no atomics).
        hupd(hw, 0,  i0, lane);
        hupd(hw, 2,  i1, lane);
        hupd(hw, 4,  i2, lane);
        hupd(hw, 6,  i3, lane);
        hupd(hw, 17, i4, lane);
        hupd(hw, 51, jcur.x, lane);
        hupd(hw, 70, jcur.y, lane);

        // Stage for broadcast consumption.
        stX[w][buf][lane] = make_float4(p0, ccur.x, p1, ccur.y);
        stY[w][buf][lane] = make_float2(p2, 0.f);
        __syncwarp();

        // Scalar j-loop: 2 LDS broadcasts + 5 FMA + 2 FMNMX + 2 FADD per token.
        #pragma unroll 8
        for (int j = 0; j < nv; j++) {
            const float4 x = stX[w][buf][j];
            const float2 y = stY[w][buf][j];
            const float tp = fmaf(y.x, wp2, fmaf(x.z, wp1, fmaf(x.x, wp0, bp)));
            const float tc = fmaf(x.w, wc1, fmaf(x.y, wc0, bc));
            accp += fmaxf(tp, 0.f);
            accc += fmaxf(tc, 0.f);
        }

        if (!have_next) break;
        t0 += 32;
        buf ^= 1;
    }

    // ---- per-warp epilogue (lane = channel d) ----
    const float invlen = 1.0f / (float)len;
    const int d = lane;

    // Second linears: broadcast pooled pre-activations via SHFL.
    const float up = accp * invlen;
    const float uc = accc * invlen;
    float hp = b_p2[d], hc = b_c2[d];
    #pragma unroll
    for (int e = 0; e < 32; e++) {
        hp = fmaf(__shfl_sync(FULL, up, e), w_p2[e * 32 + d], hp);
        hc = fmaf(__shfl_sync(FULL, uc, e), w_c2[e * 32 + d], hc);
    }

    // Embedding means from histogram counts (2 accumulators for ILP).
    float sa = 0.f, sb = 0.f;
    #pragma unroll
    for (int v = 0; v < 2; v++)  sa = fmaf((float)hw[v],      emb_gender[v * 32 + d], sa);
    #pragma unroll
    for (int v = 0; v < 2; v++)  sb = fmaf((float)hw[2 + v],  emb_korean[v * 32 + d], sb);
    #pragma unroll
    for (int v = 0; v < 2; v++)  sa = fmaf((float)hw[4 + v],  emb_primary[v * 32 + d], sa);
    #pragma unroll
    for (int v = 0; v < 11; v++) {
        if (v & 1) sb = fmaf((float)hw[6 + v], emb_job[v * 32 + d], sb);
        else       sa = fmaf((float)hw[6 + v], emb_job[v * 32 + d], sa);
    }
    #pragma unroll
    for (int v = 0; v < 34; v++) {
        if (v & 1) sb = fmaf((float)hw[17 + v], emb_rep[v * 32 + d], sb);
        else       sa = fmaf((float)hw[17 + v], emb_rep[v * 32 + d], sa);
    }
    const float ep = (sa + sb) * invlen * 0.2f;

    float ta = 0.f, tb = 0.f;
    #pragma unroll
    for (int v = 0; v < 19; v++) {
        if (v & 1) tb = fmaf((float)hw[51 + v], emb_place[v * 32 + d], tb);
        else       ta = fmaf((float)hw[51 + v], emb_place[v * 32 + d], ta);
    }
    #pragma unroll
    for (int v = 0; v < 31; v++) {
        if (v & 1) tb = fmaf((float)hw[70 + v], emb_add[v * 32 + d], tb);
        else       ta = fmaf((float)hw[70 + v], emb_add[v * 32 + d], ta);
    }
    const float ec = (ta + tb) * invlen * 0.5f;

    // Stage pooled vector x = [ep | ec | hp | hc] in warp-private shared.
    float* xb = reinterpret_cast<float*>(xb4[w]);
    xb[d] = ep; xb[32 + d] = ec; xb[64 + d] = hp; xb[96 + d] = hc;
    __syncwarp();

    // fc1: 128 -> 64 (2 outputs per lane); x via float4 LDS, split accumulators.
    float a0a = b_fc1[d],      a0b = 0.f;
    float a1a = b_fc1[32 + d], a1b = 0.f;
    #pragma unroll 8
    for (int i = 0; i < 128; i += 4) {
        const float4 xv = xb4[w][i >> 2];
        a0a = fmaf(xv.x, w_fc1[i * 64 + d], a0a);
        a1a = fmaf(xv.x, w_fc1[i * 64 + 32 + d], a1a);
        a0b = fmaf(xv.y, w_fc1[(i + 1) * 64 + d], a0b);
        a1b = fmaf(xv.y, w_fc1[(i + 1) * 64 + 32 + d], a1b);
        a0a = fmaf(xv.z, w_fc1[(i + 2) * 64 + d], a0a);
        a1a = fmaf(xv.z, w_fc1[(i + 2) * 64 + 32 + d], a1a);
        a0b = fmaf(xv.w, w_fc1[(i + 3) * 64 + d], a0b);
        a1b = fmaf(xv.w, w_fc1[(i + 3) * 64 + 32 + d], a1b);
    }
    const float h0 = fmaxf(a0a + a0b, 0.f);
    const float h1 = fmaxf(a1a + a1b, 0.f);

    // fc2: 64 -> 2, warp tree-reduce.
    float s0 = h0 * w_fc2[d * 2]     + h1 * w_fc2[(32 + d) * 2];
    float s1 = h0 * w_fc2[d * 2 + 1] + h1 * w_fc2[(32 + d) * 2 + 1];
    #pragma unroll
    for (int off = 16; off; off >>= 1) {
        s0 += __shfl_xor_sync(FULL, s0, off);
        s1 += __shfl_xor_sync(FULL, s1, off);
    }
    if (lane == 0) {
        out[row * 2]     = fmaxf(s0 + b_fc2[0], 0.f);
        out[row * 2 + 1] = fmaxf(s1 + b_fc2[1], 0.f);
    }
}

extern "C" void kernel_launch(void* const* d_in, const int* in_sizes, int n_in,
                              void* d_out, int out_size)
{
    const float* cont_p   = (const float*)d_in[0];
    const float* cont_c   = (const float*)d_in[1];
    const int*   cat_p    = (const int*)  d_in[2];
    const int*   cat_c    = (const int*)  d_in[3];
    const int*   lengths  = (const int*)  d_in[4];
    const float* w_p1     = (const float*)d_in[5];
    const float* b_p1     = (const float*)d_in[6];
    const float* w_p2     = (const float*)d_in[7];
    const float* b_p2     = (const float*)d_in[8];
    const float* w_c1     = (const float*)d_in[9];
    const float* b_c1     = (const float*)d_in[10];
    const float* w_c2     = (const float*)d_in[11];
    const float* b_c2     = (const float*)d_in[12];
    const float* emb_gender  = (const float*)d_in[13];
    const float* emb_korean  = (const float*)d_in[14];
    const float* emb_primary = (const float*)d_in[15];
    const float* emb_job     = (const float*)d_in[16];
    const float* emb_rep     = (const float*)d_in[17];
    const float* emb_place   = (const float*)d_in[18];
    const float* emb_add     = (const float*)d_in[19];
    const float* w_fc1    = (const float*)d_in[20];
    const float* b_fc1    = (const float*)d_in[21];
    const float* w_fc2    = (const float*)d_in[22];
    const float* b_fc2    = (const float*)d_in[23];
    float* out = (float*)d_out;

    const int B = in_sizes[4];                 // lengths: [B]
    const int S = in_sizes[0] / (B * 3);       // cont_p: [B,S,3]

    const int grid = (B + 3) / 4;              // one warp per row, 4 rows/block
    mlp_row_kernel<<<grid, 128>>>(cont_p, cont_c, cat_p, cat_c, lengths,
                                  w_p1, b_p1, w_p2, b_p2, w_c1, b_c1, w_c2, b_c2,
                                  emb_gender, emb_korean, emb_primary, emb_job,
                                  emb_rep, emb_place, emb_add,
                                  w_fc1, b_fc1, w_fc2, b_fc2, out, S, B);
}